// round 6
// baseline (speedup 1.0000x reference)
#include <cuda_runtime.h>
#include <stdint.h>

#define NTOK 8192
#define DM   2048
#define NE   8
#define FE   1024
#define FS   2048

// ---------------- scratch (device globals; no allocation) ----------------
__device__ float g_comb[NTOK * NE];
__device__ float g_sg[NTOK];
__device__ int   g_top[NTOK * 2];
__device__ int   g_cnt[NE];
__device__ int   g_list[NE * NTOK];
__device__ float g_acte[(size_t)NE * NTOK * FE];   // per-expert act scratch (compact rows)
__device__ float g_acts[(size_t)NTOK * FS];        // shared-expert act scratch
__device__ float g_wTg[(size_t)NE * FE * DM];      // w_gate^T  [e][F][D], tf32-rounded
__device__ float g_wTu[(size_t)NE * FE * DM];      // w_up^T
__device__ float g_wTd[(size_t)NE * DM * FE];      // w_down^T  [e][D][F]
__device__ float g_wsTg[(size_t)FS * DM];
__device__ float g_wsTu[(size_t)FS * DM];
__device__ float g_wsTd[(size_t)DM * FS];

// ---------------- helpers ----------------
__device__ __forceinline__ uint32_t f2tf(float x) {
    uint32_t r;
    asm("cvt.rna.tf32.f32 %0, %1;" : "=r"(r) : "f"(x));
    return r;
}
__device__ __forceinline__ float tf32r(float x) { return __uint_as_float(f2tf(x)); }

__device__ __forceinline__ void mma8(float* c, const uint32_t* a, const uint32_t* b) {
    asm volatile(
        "mma.sync.aligned.m16n8k8.row.col.f32.tf32.tf32.f32 "
        "{%0,%1,%2,%3},{%4,%5,%6,%7},{%8,%9},{%0,%1,%2,%3};"
        : "+f"(c[0]), "+f"(c[1]), "+f"(c[2]), "+f"(c[3])
        : "r"(a[0]), "r"(a[1]), "r"(a[2]), "r"(a[3]), "r"(b[0]), "r"(b[1]));
}

// ---------------- prep: transpose weights to [n][k], round to tf32 ----------------
__global__ void transpose_kernel(const float* __restrict__ w_gate, const float* __restrict__ w_up,
                                 const float* __restrict__ w_down, const float* __restrict__ ws_gate,
                                 const float* __restrict__ ws_up, const float* __restrict__ ws_down) {
    __shared__ float tile[32][33];
    int z = blockIdx.z;
    const float* in; float* out; int R, C;
    if (z < 8)       { in = w_gate + (size_t)z * DM * FE;        out = g_wTg + (size_t)z * FE * DM;        R = DM; C = FE; }
    else if (z < 16) { in = w_up   + (size_t)(z - 8) * DM * FE;  out = g_wTu + (size_t)(z - 8) * FE * DM;  R = DM; C = FE; }
    else if (z < 24) { in = w_down + (size_t)(z - 16) * FE * DM; out = g_wTd + (size_t)(z - 16) * DM * FE; R = FE; C = DM; }
    else if (z == 24){ in = ws_gate; out = g_wsTg; R = DM; C = FS; }
    else if (z == 25){ in = ws_up;   out = g_wsTu; R = DM; C = FS; }
    else             { in = ws_down; out = g_wsTd; R = FS; C = DM; }
    int cx = blockIdx.x * 32, ry = blockIdx.y * 32;
    if (cx >= C || ry >= R) return;
    int tx = threadIdx.x, ty = threadIdx.y;
#pragma unroll
    for (int j = 0; j < 32; j += 8)
        tile[ty + j][tx] = in[(size_t)(ry + ty + j) * C + cx + tx];
    __syncthreads();
#pragma unroll
    for (int j = 0; j < 32; j += 8)
        out[(size_t)(cx + ty + j) * R + ry + tx] = tf32r(tile[tx][ty + j]);
}

// ---------------- router ----------------
__global__ void router_kernel(const float* __restrict__ h,
                              const float* __restrict__ gw,
                              const float* __restrict__ wsg) {
    int lane = threadIdx.x & 31;
    int t = blockIdx.x * (blockDim.x >> 5) + (threadIdx.x >> 5);
    if (t >= NTOK) return;
    const float* hr = h + (size_t)t * DM;
    float acc[8];
#pragma unroll
    for (int i = 0; i < 8; i++) acc[i] = 0.f;
    float as_ = 0.f;
    for (int d = lane; d < DM; d += 32) {
        float hv = hr[d];
        const float4* gr = reinterpret_cast<const float4*>(gw + (size_t)d * NE);
        float4 g0 = gr[0], g1 = gr[1];
        acc[0] += hv * g0.x; acc[1] += hv * g0.y; acc[2] += hv * g0.z; acc[3] += hv * g0.w;
        acc[4] += hv * g1.x; acc[5] += hv * g1.y; acc[6] += hv * g1.z; acc[7] += hv * g1.w;
        as_ += hv * wsg[d];
    }
#pragma unroll
    for (int o = 16; o; o >>= 1) {
#pragma unroll
        for (int i = 0; i < 8; i++) acc[i] += __shfl_xor_sync(0xffffffffu, acc[i], o);
        as_ += __shfl_xor_sync(0xffffffffu, as_, o);
    }
    if (lane == 0) {
        int i1 = 0;
#pragma unroll
        for (int e = 1; e < 8; e++) if (acc[e] > acc[i1]) i1 = e;
        int i2 = -1;
#pragma unroll
        for (int e = 0; e < 8; e++) {
            if (e == i1) continue;
            if (i2 < 0 || acc[e] > acc[i2]) i2 = e;
        }
        float e2 = __expf(acc[i2] - acc[i1]);
        float w1 = 1.f / (1.f + e2);
        float w2 = e2 / (1.f + e2);
#pragma unroll
        for (int e = 0; e < 8; e++)
            g_comb[t * NE + e] = (e == i1) ? w1 : ((e == i2) ? w2 : 0.f);
        g_top[t * 2] = i1;
        g_top[t * 2 + 1] = i2;
        g_sg[t] = 1.f / (1.f + __expf(-as_));
    }
}

__global__ void build_lists_kernel() {
    int e = blockIdx.x;
    int tid = threadIdx.x;
    __shared__ int warp_cnt[8];
    __shared__ int s_base;
    if (tid == 0) s_base = 0;
    __syncthreads();
    for (int base = 0; base < NTOK; base += 256) {
        int t = base + tid;
        int flag = (g_top[t * 2] == e) || (g_top[t * 2 + 1] == e);
        unsigned bal = __ballot_sync(0xffffffffu, flag);
        int lane = tid & 31, w = tid >> 5;
        if (lane == 0) warp_cnt[w] = __popc(bal);
        __syncthreads();
        int off = 0;
        for (int i = 0; i < w; i++) off += warp_cnt[i];
        int pos = s_base + off + __popc(bal & ((1u << lane) - 1u));
        if (flag) g_list[e * NTOK + pos] = t;
        __syncthreads();
        if (tid == 0) {
            int tot = 0;
            for (int i = 0; i < 8; i++) tot += warp_cnt[i];
            s_base += tot;
        }
        __syncthreads();
    }
    if (tid == 0) g_cnt[e] = s_base;
}

// ====================================================================
// Fragment-major GEMM core.
// A blocks: [s(0..3)][mt(0..7)] x 32 lanes x 16B = the exact mma A-frag per lane.
//   lane(grp,tg) 16B = { (m=16mt+grp, k=8s+tg), (m+8,k), (m,k+4), (m+8,k+4) }.
// B blocks: [s2(0..1)][nt] x 32 lanes x 16B = 4 regs covering 2 k-slabs.
//   lane(grp,tg) 16B = { k=16s2+tg, +4, +8, +12 } at n=8nt+grp.
// Stage stride = 12288 words (48KB): A @0, B1 @4096, B2 @8192 (gemm2: B @4096).
// ====================================================================

// ---------------- GEMM1: act = silu(X@Wg^T)*(X@Wu^T); M=128 N=128 BK=32 ------
#define G1_LDG()                                                                   \
    {                                                                              \
        _Pragma("unroll") for (int j = 0; j < 4; j++)                              \
            va[j] = *(const float4*)(Arow + k0 + 8 * j);                           \
        _Pragma("unroll") for (int jj = 0; jj < 4; jj++) {                         \
            v1[jj] = *(const float4*)(Bs1[jj] + k0);                               \
            v2[jj] = *(const float4*)(Bs2[jj] + k0);                               \
        }                                                                          \
    }

#define G1_STS(B_)                                                                 \
    {                                                                              \
        uint32_t* S = sm + (B_)*12288;                                             \
        _Pragma("unroll") for (int j = 0; j < 4; j++) {                            \
            const float* f = &va[j].x;                                             \
            _Pragma("unroll") for (int js = 0; js < 4; js++) {                     \
                int tt = (js + arot) & 3;                                          \
                S[adst + j * 1024 + tt * 4] = f2tf(f[tt]);                         \
            }                                                                      \
        }                                                                          \
        uint32_t* S1 = S + 4096;                                                   \
        uint32_t* S2 = S + 8192;                                                   \
        _Pragma("unroll") for (int jj = 0; jj < 4; jj++) {                         \
            const float* f1 = &v1[jj].x;                                           \
            const float* f2 = &v2[jj].x;                                           \
            _Pragma("unroll") for (int js = 0; js < 4; js++) {                     \
                int tt = (js + brot) & 3;                                          \
                S1[bdst[jj] + tt * 4] = __float_as_uint(f1[tt]);                   \
                S2[bdst[jj] + tt * 4] = __float_as_uint(f2[tt]);                   \
            }                                                                      \
        }                                                                          \
    }

#define G1_COMP(B_)                                                                \
    {                                                                              \
        const uint32_t* SA = sm + (B_)*12288 + afrag;                              \
        const uint32_t* SB1 = sm + (B_)*12288 + 4096 + bfrag;                      \
        const uint32_t* SB2 = sm + (B_)*12288 + 8192 + bfrag;                      \
        _Pragma("unroll") for (int s2 = 0; s2 < 2; s2++) {                         \
            uint32_t bf1[4][4], bf2[4][4];                                         \
            _Pragma("unroll") for (int in = 0; in < 4; in++) {                     \
                *(uint4*)bf1[in] = *(const uint4*)(SB1 + s2 * 2048 + in * 128);    \
                *(uint4*)bf2[in] = *(const uint4*)(SB2 + s2 * 2048 + in * 128);    \
            }                                                                      \
            _Pragma("unroll") for (int ps = 0; ps < 2; ps++) {                     \
                uint32_t af[4][4];                                                 \
                _Pragma("unroll") for (int im = 0; im < 4; im++)                   \
                    *(uint4*)af[im] =                                              \
                        *(const uint4*)(SA + (s2 * 2 + ps) * 1024 + im * 128);     \
                _Pragma("unroll") for (int im = 0; im < 4; im++)                   \
                    _Pragma("unroll") for (int in = 0; in < 4; in++) {             \
                        mma8(c1[im][in], af[im], &bf1[in][2 * ps]);                \
                        mma8(c2[im][in], af[im], &bf2[in][2 * ps]);                \
                    }                                                              \
            }                                                                      \
        }                                                                          \
    }

template <bool EXPERT>
__global__ __launch_bounds__(256, 1)
void gemm1_kernel(const float* __restrict__ h) {
    extern __shared__ uint32_t sm[];
    const int e = EXPERT ? blockIdx.z : 0;
    const int M = EXPERT ? g_cnt[e] : NTOK;
    const int row0 = blockIdx.y * 128;
    if (row0 >= M) return;
    const int n0 = blockIdx.x * 128;
    const float* B1 = EXPERT ? (g_wTg + (size_t)e * FE * DM) : g_wsTg;
    const float* B2 = EXPERT ? (g_wTu + (size_t)e * FE * DM) : g_wsTu;
    float* C = EXPERT ? (g_acte + (size_t)e * NTOK * FE) : g_acts;
    const int ldc = EXPERT ? FE : FS;
    const int* rl = g_list + e * NTOK;

    const int tid = threadIdx.x, l = tid & 31, w = tid >> 5;

    // --- A staging map: warp w -> m-tile w; j -> k-slab; lane -> (g,hi,p)
    const int ag = l & 7, ahi = (l >> 3) & 1, ap = (l >> 4) & 1;
    const float* Arow;
    {
        int r = row0 + 16 * w + 8 * ahi + ag;
        int rr = r < M ? r : row0;
        int sr = EXPERT ? rl[rr] : rr;
        Arow = h + (size_t)sr * DM + 4 * ap;
    }
    const int adst = w * 128 + ag * 16 + 2 * ap + ahi;
    const int arot = ag >> 1;

    // --- B staging map: warp w -> nt {2w,2w+1} x s2 {0,1}; lane -> (g,q)
    const int bg = l & 7, bq = (l >> 3) & 3;
    const float* Bs1[4];
    const float* Bs2[4];
    int bdst[4];
#pragma unroll
    for (int jj = 0; jj < 4; jj++) {
        int s2 = jj & 1, nt = 2 * w + (jj >> 1);
        size_t off = (size_t)(n0 + nt * 8 + bg) * DM + 16 * s2 + 4 * bq;
        Bs1[jj] = B1 + off;
        Bs2[jj] = B2 + off;
        bdst[jj] = (s2 * 16 + nt) * 128 + bg * 16 + bq;
    }
    const int brot = bg >> 1;

    // --- compute maps
    const int wm_i = w >> 2, wn_i = w & 3, grp = l >> 2, tg = l & 3;
    const int afrag = wm_i * 512 + l * 4;
    const int bfrag = wn_i * 512 + l * 4;

    float c1[4][4][4], c2[4][4][4];
#pragma unroll
    for (int i = 0; i < 4; i++)
#pragma unroll
        for (int j = 0; j < 4; j++)
#pragma unroll
            for (int q = 0; q < 4; q++) { c1[i][j][q] = 0.f; c2[i][j][q] = 0.f; }

    float4 va[4], v1[4], v2[4];
    int k0 = 0;
    G1_LDG()
    G1_STS(0)
    __syncthreads();
    const int T = DM / 32;
    for (int t = 0; t < T; t++) {
        int cur = t & 1;
        if (t + 1 < T) { k0 = (t + 1) * 32; G1_LDG() }
        G1_COMP(cur)
        if (t + 1 < T) G1_STS(1 - cur)
        __syncthreads();
    }

    // epilogue: silu(gate)*up, rounded to tf32 so gemm2 staging is a pure copy
#pragma unroll
    for (int im = 0; im < 4; im++) {
        int r = row0 + wm_i * 64 + im * 16 + grp;
#pragma unroll
        for (int in = 0; in < 4; in++) {
            int cc = n0 + wn_i * 32 + in * 8 + 2 * tg;
            if (r < M) {
                float g0 = c1[im][in][0], u0 = c2[im][in][0];
                float g1 = c1[im][in][1], u1 = c2[im][in][1];
                float2 o;
                o.x = tf32r(g0 * (1.f / (1.f + __expf(-g0))) * u0);
                o.y = tf32r(g1 * (1.f / (1.f + __expf(-g1))) * u1);
                *reinterpret_cast<float2*>(&C[(size_t)r * ldc + cc]) = o;
            }
            if (r + 8 < M) {
                float g0 = c1[im][in][2], u0 = c2[im][in][2];
                float g1 = c1[im][in][3], u1 = c2[im][in][3];
                float2 o;
                o.x = tf32r(g0 * (1.f / (1.f + __expf(-g0))) * u0);
                o.y = tf32r(g1 * (1.f / (1.f + __expf(-g1))) * u1);
                *reinterpret_cast<float2*>(&C[(size_t)(r + 8) * ldc + cc]) = o;
            }
        }
    }
}

// ---------------- GEMM2: out (+)= scale*(act @ Wd^T); M=128 N=256 BK=32 ------
#define G2_LDG()                                                                   \
    {                                                                              \
        _Pragma("unroll") for (int j = 0; j < 4; j++)                              \
            va[j] = *(const float4*)(Arow + k0 + 8 * j);                           \
        _Pragma("unroll") for (int jj = 0; jj < 8; jj++)                           \
            vb[jj] = *(const float4*)(Bs[jj] + k0);                                \
    }

#define G2_STS(B_)                                                                 \
    {                                                                              \
        uint32_t* S = sm + (B_)*12288;                                             \
        _Pragma("unroll") for (int j = 0; j < 4; j++) {                            \
            const float* f = &va[j].x;                                             \
            _Pragma("unroll") for (int js = 0; js < 4; js++) {                     \
                int tt = (js + arot) & 3;                                          \
                S[adst + j * 1024 + tt * 4] = __float_as_uint(f[tt]);              \
            }                                                                      \
        }                                                                          \
        uint32_t* SB = S + 4096;                                                   \
        _Pragma("unroll") for (int jj = 0; jj < 8; jj++) {                         \
            const float* f = &vb[jj].x;                                            \
            _Pragma("unroll") for (int js = 0; js < 4; js++) {                     \
                int tt = (js + brot) & 3;                                          \
                SB[bdst[jj] + tt * 4] = __float_as_uint(f[tt]);                    \
            }                                                                      \
        }                                                                          \
    }

#define G2_COMP(B_)                                                                \
    {                                                                              \
        const uint32_t* SA = sm + (B_)*12288 + afrag;                              \
        const uint32_t* SB = sm + (B_)*12288 + 4096 + bfrag;                       \
        _Pragma("unroll") for (int s2 = 0; s2 < 2; s2++) {                         \
            uint32_t bf[8][4];                                                     \
            _Pragma("unroll") for (int in = 0; in < 8; in++)                       \
                *(uint4*)bf[in] = *(const uint4*)(SB + s2 * 4096 + in * 128);      \
            _Pragma("unroll") for (int ps = 0; ps < 2; ps++) {                     \
                uint32_t af[4][4];                                                 \
                _Pragma("unroll") for (int im = 0; im < 4; im++)                   \
                    *(uint4*)af[im] =                                              \
                        *(const uint4*)(SA + (s2 * 2 + ps) * 1024 + im * 128);     \
                _Pragma("unroll") for (int im = 0; im < 4; im++)                   \
                    _Pragma("unroll") for (int in = 0; in < 8; in++)               \
                        mma8(c[im][in], af[im], &bf[in][2 * ps]);                  \
            }                                                                      \
        }                                                                          \
    }

template <bool EXPERT>
__global__ __launch_bounds__(256, 1)
void gemm2_kernel(float* __restrict__ out) {
    extern __shared__ uint32_t sm[];
    const int e = EXPERT ? blockIdx.z : 0;
    const int M = EXPERT ? g_cnt[e] : NTOK;
    const int row0 = blockIdx.y * 128;
    if (row0 >= M) return;
    const int n0 = blockIdx.x * 256;
    const int K = EXPERT ? FE : FS;
    const float* Aact = EXPERT ? (g_acte + (size_t)e * NTOK * FE) : g_acts;
    const float* B = EXPERT ? (g_wTd + (size_t)e * DM * FE) : g_wsTd;
    const int* rl = g_list + e * NTOK;

    const int tid = threadIdx.x, l = tid & 31, w = tid >> 5;

    const int ag = l & 7, ahi = (l >> 3) & 1, ap = (l >> 4) & 1;
    const float* Arow = Aact + (size_t)(row0 + 16 * w + 8 * ahi + ag) * K + 4 * ap;
    const int adst = w * 128 + ag * 16 + 2 * ap + ahi;
    const int arot = ag >> 1;

    const int bg = l & 7, bq = (l >> 3) & 3;
    const float* Bs[8];
    int bdst[8];
#pragma unroll
    for (int jj = 0; jj < 8; jj++) {
        int s2 = jj & 1, nt = 4 * w + (jj >> 1);
        Bs[jj] = B + (size_t)(n0 + nt * 8 + bg) * K + 16 * s2 + 4 * bq;
        bdst[jj] = (s2 * 32 + nt) * 128 + bg * 16 + bq;
    }
    const int brot = bg >> 1;

    const int wm_i = w >> 2, wn_i = w & 3, grp = l >> 2, tg = l & 3;
    const int afrag = wm_i * 512 + l * 4;
    const int bfrag = wn_i * 1024 + l * 4;

    float c[4][8][4];
#pragma unroll
    for (int i = 0; i < 4; i++)
#pragma unroll
        for (int j = 0; j < 8; j++)
#pragma unroll
            for (int q = 0; q < 4; q++) c[i][j][q] = 0.f;

    float4 va[4], vb[8];
    int k0 = 0;
    G2_LDG()
    G2_STS(0)
    __syncthreads();
    const int T = K / 32;
    for (int t = 0; t < T; t++) {
        int cur = t & 1;
        if (t + 1 < T) { k0 = (t + 1) * 32; G2_LDG() }
        G2_COMP(cur)
        if (t + 1 < T) G2_STS(1 - cur)
        __syncthreads();
    }

    // epilogue
#pragma unroll
    for (int im = 0; im < 4; im++) {
        int r = row0 + wm_i * 64 + im * 16 + grp;
        int tok0 = 0, tok1 = 0;
        float s0 = 0.f, s1 = 0.f;
        if (EXPERT) {
            if (r < M)     { tok0 = rl[r];     s0 = g_comb[tok0 * NE + e]; }
            if (r + 8 < M) { tok1 = rl[r + 8]; s1 = g_comb[tok1 * NE + e]; }
        } else {
            if (r < M)     s0 = g_sg[r];
            if (r + 8 < M) s1 = g_sg[r + 8];
        }
#pragma unroll
        for (int in = 0; in < 8; in++) {
            int cc = n0 + wn_i * 64 + in * 8 + 2 * tg;
            if (r < M) {
                if (EXPERT) {
                    atomicAdd(&out[(size_t)tok0 * DM + cc],     s0 * c[im][in][0]);
                    atomicAdd(&out[(size_t)tok0 * DM + cc + 1], s0 * c[im][in][1]);
                } else {
                    float2 o; o.x = s0 * c[im][in][0]; o.y = s0 * c[im][in][1];
                    *reinterpret_cast<float2*>(&out[(size_t)r * DM + cc]) = o;
                }
            }
            if (r + 8 < M) {
                if (EXPERT) {
                    atomicAdd(&out[(size_t)tok1 * DM + cc],     s1 * c[im][in][2]);
                    atomicAdd(&out[(size_t)tok1 * DM + cc + 1], s1 * c[im][in][3]);
                } else {
                    float2 o; o.x = s1 * c[im][in][2]; o.y = s1 * c[im][in][3];
                    *reinterpret_cast<float2*>(&out[(size_t)(r + 8) * DM + cc]) = o;
                }
            }
        }
    }
}

// ---------------- launch ----------------
#define SMEM_BYTES 98304   // 2 stages x 48KB

extern "C" void kernel_launch(void* const* d_in, const int* in_sizes, int n_in,
                              void* d_out, int out_size) {
    const float* h       = (const float*)d_in[0];
    const float* gate_w  = (const float*)d_in[1];
    const float* w_gate  = (const float*)d_in[2];
    const float* w_up    = (const float*)d_in[3];
    const float* w_down  = (const float*)d_in[4];
    const float* ws_gate = (const float*)d_in[5];
    const float* ws_up   = (const float*)d_in[6];
    const float* ws_down = (const float*)d_in[7];
    const float* wsg     = (const float*)d_in[8];
    float* out = (float*)d_out;

    cudaFuncSetAttribute(gemm1_kernel<false>, cudaFuncAttributeMaxDynamicSharedMemorySize, SMEM_BYTES);
    cudaFuncSetAttribute(gemm1_kernel<true>,  cudaFuncAttributeMaxDynamicSharedMemorySize, SMEM_BYTES);
    cudaFuncSetAttribute(gemm2_kernel<false>, cudaFuncAttributeMaxDynamicSharedMemorySize, SMEM_BYTES);
    cudaFuncSetAttribute(gemm2_kernel<true>,  cudaFuncAttributeMaxDynamicSharedMemorySize, SMEM_BYTES);

    transpose_kernel<<<dim3(64, 64, 27), dim3(32, 8)>>>(w_gate, w_up, w_down, ws_gate, ws_up, ws_down);
    router_kernel<<<NTOK / 8, 256>>>(h, gate_w, wsg);
    build_lists_kernel<<<NE, 256>>>();

    gemm1_kernel<false><<<dim3(FS / 128, NTOK / 128), 256, SMEM_BYTES>>>(h);
    gemm1_kernel<true><<<dim3(FE / 128, NTOK / 128, NE), 256, SMEM_BYTES>>>(h);
    gemm2_kernel<false><<<dim3(DM / 256, NTOK / 128), 256, SMEM_BYTES>>>(out);
    gemm2_kernel<true><<<dim3(DM / 256, NTOK / 128, NE), 256, SMEM_BYTES>>>(out);
}

// round 7
// speedup vs baseline: 2.0775x; 2.0775x over previous
#include <cuda_runtime.h>
#include <stdint.h>

#define NTOK 8192
#define DM   2048
#define NE   8
#define FE   1024
#define FS   2048

// ---------------- scratch (device globals; no allocation) ----------------
__device__ float g_comb[NTOK * NE];
__device__ float g_sg[NTOK];
__device__ int   g_top[NTOK * 2];
__device__ int   g_cnt[NE];
__device__ int   g_list[NE * NTOK];
__device__ float g_acte[(size_t)NE * NTOK * FE];   // per-expert act (compact rows, tf32-rounded)
__device__ float g_acts[(size_t)NTOK * FS];        // shared-expert act (tf32-rounded)
__device__ float g_ht[(size_t)NTOK * DM];          // tf32-rounded h
// tf32-rounded weights, ORIGINAL layouts
__device__ float g_wg[(size_t)NE * DM * FE];
__device__ float g_wu[(size_t)NE * DM * FE];
__device__ float g_wd[(size_t)NE * FE * DM];
__device__ float g_wsg2[(size_t)DM * FS];
__device__ float g_wsu[(size_t)DM * FS];
__device__ float g_wsd[(size_t)FS * DM];

// ---------------- helpers ----------------
__device__ __forceinline__ uint32_t f2tf(float x) {
    uint32_t r;
    asm("cvt.rna.tf32.f32 %0, %1;" : "=r"(r) : "f"(x));
    return r;
}
__device__ __forceinline__ float tf32r(float x) { return __uint_as_float(f2tf(x)); }
__device__ __forceinline__ uint32_t au(float x) { return __float_as_uint(x); }
__device__ __forceinline__ uint32_t smem_u32(const void* p) {
    uint32_t a;
    asm("{ .reg .u64 t; cvta.to.shared.u64 t, %1; cvt.u32.u64 %0, t; }" : "=r"(a) : "l"(p));
    return a;
}

__device__ __forceinline__ void mma8(float* c, const uint32_t* a, const uint32_t* b) {
    asm volatile(
        "mma.sync.aligned.m16n8k8.row.col.f32.tf32.tf32.f32 "
        "{%0,%1,%2,%3},{%4,%5,%6,%7},{%8,%9},{%0,%1,%2,%3};"
        : "+f"(c[0]), "+f"(c[1]), "+f"(c[2]), "+f"(c[3])
        : "r"(a[0]), "r"(a[1]), "r"(a[2]), "r"(a[3]), "r"(b[0]), "r"(b[1]));
}

#define CP16(dst, src) \
    asm volatile("cp.async.cg.shared.global [%0], [%1], 16;" :: "r"(dst), "l"(src) : "memory")
#define CP16Z(dst, src, sz) \
    asm volatile("cp.async.cg.shared.global [%0], [%1], 16, %2;" :: "r"(dst), "l"(src), "r"(sz) : "memory")
#define CPCOMMIT() asm volatile("cp.async.commit_group;" ::: "memory")
#define CPWAIT(n)  asm volatile("cp.async.wait_group %0;" :: "n"(n) : "memory")

// ---------------- prep: tf32-round inputs/weights (layout preserved) ----------------
__global__ void round_kernel(const float* __restrict__ h, const float* __restrict__ w_gate,
                             const float* __restrict__ w_up, const float* __restrict__ w_down,
                             const float* __restrict__ ws_gate, const float* __restrict__ ws_up,
                             const float* __restrict__ ws_down) {
    int which = blockIdx.y;
    const float* in; float* out; size_t n;
    switch (which) {
        case 0: in = h;       out = g_ht;   n = (size_t)NTOK * DM;     break;
        case 1: in = w_gate;  out = g_wg;   n = (size_t)NE * DM * FE;  break;
        case 2: in = w_up;    out = g_wu;   n = (size_t)NE * DM * FE;  break;
        case 3: in = w_down;  out = g_wd;   n = (size_t)NE * FE * DM;  break;
        case 4: in = ws_gate; out = g_wsg2; n = (size_t)DM * FS;       break;
        case 5: in = ws_up;   out = g_wsu;  n = (size_t)DM * FS;       break;
        default:in = ws_down; out = g_wsd;  n = (size_t)FS * DM;       break;
    }
    size_t n4 = n >> 2;
    for (size_t i = (size_t)blockIdx.x * blockDim.x + threadIdx.x; i < n4;
         i += (size_t)gridDim.x * blockDim.x) {
        float4 v = reinterpret_cast<const float4*>(in)[i];
        v.x = tf32r(v.x); v.y = tf32r(v.y); v.z = tf32r(v.z); v.w = tf32r(v.w);
        reinterpret_cast<float4*>(out)[i] = v;
    }
}

// ---------------- router ----------------
__global__ void router_kernel(const float* __restrict__ h,
                              const float* __restrict__ gw,
                              const float* __restrict__ wsg) {
    int lane = threadIdx.x & 31;
    int t = blockIdx.x * (blockDim.x >> 5) + (threadIdx.x >> 5);
    if (t >= NTOK) return;
    const float* hr = h + (size_t)t * DM;
    float acc[8];
#pragma unroll
    for (int i = 0; i < 8; i++) acc[i] = 0.f;
    float as_ = 0.f;
    for (int d = lane; d < DM; d += 32) {
        float hv = hr[d];
        const float4* gr = reinterpret_cast<const float4*>(gw + (size_t)d * NE);
        float4 g0 = gr[0], g1 = gr[1];
        acc[0] += hv * g0.x; acc[1] += hv * g0.y; acc[2] += hv * g0.z; acc[3] += hv * g0.w;
        acc[4] += hv * g1.x; acc[5] += hv * g1.y; acc[6] += hv * g1.z; acc[7] += hv * g1.w;
        as_ += hv * wsg[d];
    }
#pragma unroll
    for (int o = 16; o; o >>= 1) {
#pragma unroll
        for (int i = 0; i < 8; i++) acc[i] += __shfl_xor_sync(0xffffffffu, acc[i], o);
        as_ += __shfl_xor_sync(0xffffffffu, as_, o);
    }
    if (lane == 0) {
        int i1 = 0;
#pragma unroll
        for (int e = 1; e < 8; e++) if (acc[e] > acc[i1]) i1 = e;
        int i2 = -1;
#pragma unroll
        for (int e = 0; e < 8; e++) {
            if (e == i1) continue;
            if (i2 < 0 || acc[e] > acc[i2]) i2 = e;
        }
        float e2 = __expf(acc[i2] - acc[i1]);
        float w1 = 1.f / (1.f + e2);
        float w2 = e2 / (1.f + e2);
#pragma unroll
        for (int e = 0; e < 8; e++)
            g_comb[t * NE + e] = (e == i1) ? w1 : ((e == i2) ? w2 : 0.f);
        g_top[t * 2] = i1;
        g_top[t * 2 + 1] = i2;
        g_sg[t] = 1.f / (1.f + __expf(-as_));
    }
}

__global__ void build_lists_kernel() {
    int e = blockIdx.x;
    int tid = threadIdx.x;
    __shared__ int warp_cnt[8];
    __shared__ int s_base;
    if (tid == 0) s_base = 0;
    __syncthreads();
    for (int base = 0; base < NTOK; base += 256) {
        int t = base + tid;
        int flag = (g_top[t * 2] == e) || (g_top[t * 2 + 1] == e);
        unsigned bal = __ballot_sync(0xffffffffu, flag);
        int lane = tid & 31, w = tid >> 5;
        if (lane == 0) warp_cnt[w] = __popc(bal);
        __syncthreads();
        int off = 0;
        for (int i = 0; i < w; i++) off += warp_cnt[i];
        int pos = s_base + off + __popc(bal & ((1u << lane) - 1u));
        if (flag) g_list[e * NTOK + pos] = t;
        __syncthreads();
        if (tid == 0) {
            int tot = 0;
            for (int i = 0; i < 8; i++) tot += warp_cnt[i];
            s_base += tot;
        }
        __syncthreads();
    }
    if (tid == 0) g_cnt[e] = s_base;
}

// =====================================================================
// SMEM layouts (floats):
//  A : [m 0..127][k 0..15], row stride 36 words (144B, 16B-aligned).
//      Fragment bank = (4*grp + tg) mod 32 -> conflict-free.
//  B : [k 0..15][n], row stride 136 (BN=128) / 264 (BN=256), both ==8 mod 32.
//      Fragment bank = (8*tg + grp) mod 32 -> conflict-free.
// =====================================================================
#define ASTR   36
#define ASZ    (128 * ASTR)          // 4608 words
#define B1STR  136
#define B1SZ   (16 * B1STR)          // 2176 words
#define B2STR  264
#define B2SZ   (16 * B2STR)          // 4224 words
#define G1_STAGE (ASZ + 2 * B1SZ)    // 8960 words
#define G2_STAGE (ASZ + B2SZ)        // 8832 words
#define SMEM_BYTES (2 * G1_STAGE * 4)  // 71680 (>= G2's 70656)

// ---------------- GEMM1: act = silu(X@Wg)*(X@Wu); M=128 N=128 BK=16 ----------
#define G1_CP(T_, BUF)                                                           \
    {                                                                            \
        const int _k0 = (T_) * 16;                                               \
        const size_t _bo = (size_t)_k0 * ldb;                                    \
        uint32_t _d = smb + (BUF) * (G1_STAGE * 4);                              \
        CP16Z(_d + adst0 * 4, Asrc0 + _k0, asz0);                                \
        CP16Z(_d + adst1 * 4, Asrc1 + _k0, asz1);                                \
        CP16(_d + (ASZ + bdst0) * 4, Bsrc1a + _bo);                              \
        CP16(_d + (ASZ + bdst1) * 4, Bsrc1b + _bo);                              \
        CP16(_d + (ASZ + B1SZ + bdst0) * 4, Bsrc2a + _bo);                       \
        CP16(_d + (ASZ + B1SZ + bdst1) * 4, Bsrc2b + _bo);                       \
    }

#define G1_COMP(BUF)                                                             \
    {                                                                            \
        const float* SA = sm + (BUF) * G1_STAGE;                                 \
        const float* SB1 = SA + ASZ;                                             \
        const float* SB2 = SB1 + B1SZ;                                           \
        _Pragma("unroll") for (int kt = 0; kt < 2; kt++) {                       \
            const int ks = kt * 8;                                               \
            uint32_t a[4][4], b1[4][2], b2[4][2];                                \
            _Pragma("unroll") for (int im = 0; im < 4; im++) {                   \
                const int m0 = wm_i * 64 + im * 16;                              \
                a[im][0] = au(SA[(m0 + grp) * ASTR + ks + tg]);                  \
                a[im][1] = au(SA[(m0 + 8 + grp) * ASTR + ks + tg]);              \
                a[im][2] = au(SA[(m0 + grp) * ASTR + ks + tg + 4]);              \
                a[im][3] = au(SA[(m0 + 8 + grp) * ASTR + ks + tg + 4]);          \
            }                                                                    \
            _Pragma("unroll") for (int in = 0; in < 4; in++) {                   \
                const int nb = wn_i * 32 + in * 8 + grp;                         \
                b1[in][0] = au(SB1[(ks + tg) * B1STR + nb]);                     \
                b1[in][1] = au(SB1[(ks + tg + 4) * B1STR + nb]);                 \
                b2[in][0] = au(SB2[(ks + tg) * B1STR + nb]);                     \
                b2[in][1] = au(SB2[(ks + tg + 4) * B1STR + nb]);                 \
            }                                                                    \
            _Pragma("unroll") for (int im = 0; im < 4; im++)                     \
                _Pragma("unroll") for (int in = 0; in < 4; in++) {               \
                    mma8(c1[im][in], a[im], b1[in]);                             \
                    mma8(c2[im][in], a[im], b2[in]);                             \
                }                                                                \
        }                                                                        \
    }

template <bool EXPERT>
__global__ __launch_bounds__(256, 1)
void gemm1_kernel() {
    extern __shared__ float sm[];
    const int e = EXPERT ? blockIdx.z : 0;
    const int M = EXPERT ? g_cnt[e] : NTOK;
    const int row0 = blockIdx.y * 128;
    if (row0 >= M) return;
    const int n0 = blockIdx.x * 128;
    const int ldb = EXPERT ? FE : FS;
    const float* B1 = EXPERT ? (g_wg + (size_t)e * DM * FE) : g_wsg2;
    const float* B2 = EXPERT ? (g_wu + (size_t)e * DM * FE) : g_wsu;
    float* C = EXPERT ? (g_acte + (size_t)e * NTOK * FE) : g_acts;
    const int* rl = g_list + e * NTOK;

    const int tid = threadIdx.x, l = tid & 31, w = tid >> 5;
    const uint32_t smb = smem_u32(sm);

    // --- staging maps ---
    // A: thread -> rows (tid>>2) and (tid>>2)+64, k-quad tid&3
    const int arow = tid >> 2, akq = tid & 3;
    const int adst0 = arow * ASTR + akq * 4;
    const int adst1 = (arow + 64) * ASTR + akq * 4;
    uint32_t asz0, asz1;
    const float* Asrc0;
    const float* Asrc1;
    {
        int r0 = row0 + arow, r1 = r0 + 64;
        asz0 = r0 < M ? 16u : 0u;
        asz1 = r1 < M ? 16u : 0u;
        int s0 = r0 < M ? (EXPERT ? rl[r0] : r0) : 0;
        int s1 = r1 < M ? (EXPERT ? rl[r1] : r1) : 0;
        Asrc0 = g_ht + (size_t)s0 * DM + akq * 4;
        Asrc1 = g_ht + (size_t)s1 * DM + akq * 4;
    }
    // B: thread -> k rows (tid>>5) and +8, n-quad tid&31
    const int bk_ = tid >> 5, bnq = tid & 31;
    const int bdst0 = bk_ * B1STR + bnq * 4;
    const int bdst1 = (bk_ + 8) * B1STR + bnq * 4;
    const float* Bsrc1a = B1 + (size_t)bk_ * ldb + n0 + bnq * 4;
    const float* Bsrc1b = B1 + (size_t)(bk_ + 8) * ldb + n0 + bnq * 4;
    const float* Bsrc2a = B2 + (size_t)bk_ * ldb + n0 + bnq * 4;
    const float* Bsrc2b = B2 + (size_t)(bk_ + 8) * ldb + n0 + bnq * 4;

    // --- compute maps ---
    const int wm_i = w >> 2, wn_i = w & 3, grp = l >> 2, tg = l & 3;

    float c1[4][4][4], c2[4][4][4];
#pragma unroll
    for (int i = 0; i < 4; i++)
#pragma unroll
        for (int j = 0; j < 4; j++)
#pragma unroll
            for (int q = 0; q < 4; q++) { c1[i][j][q] = 0.f; c2[i][j][q] = 0.f; }

    const int T = DM / 16;
    G1_CP(0, 0)
    CPCOMMIT();
    for (int t = 0; t < T; t++) {
        if (t + 1 < T) { G1_CP(t + 1, (t + 1) & 1) CPCOMMIT(); CPWAIT(1); }
        else CPWAIT(0);
        __syncthreads();
        G1_COMP(t & 1)
        __syncthreads();
    }

    // epilogue: silu(gate)*up, rounded to tf32 (so gemm2 can stage raw)
    const int ldc = ldb;
#pragma unroll
    for (int im = 0; im < 4; im++) {
        int r = row0 + wm_i * 64 + im * 16 + grp;
#pragma unroll
        for (int in = 0; in < 4; in++) {
            int cc = n0 + wn_i * 32 + in * 8 + 2 * tg;
            if (r < M) {
                float g0 = c1[im][in][0], u0 = c2[im][in][0];
                float g1 = c1[im][in][1], u1 = c2[im][in][1];
                float2 o;
                o.x = tf32r(g0 * (1.f / (1.f + __expf(-g0))) * u0);
                o.y = tf32r(g1 * (1.f / (1.f + __expf(-g1))) * u1);
                *reinterpret_cast<float2*>(&C[(size_t)r * ldc + cc]) = o;
            }
            if (r + 8 < M) {
                float g0 = c1[im][in][2], u0 = c2[im][in][2];
                float g1 = c1[im][in][3], u1 = c2[im][in][3];
                float2 o;
                o.x = tf32r(g0 * (1.f / (1.f + __expf(-g0))) * u0);
                o.y = tf32r(g1 * (1.f / (1.f + __expf(-g1))) * u1);
                *reinterpret_cast<float2*>(&C[(size_t)(r + 8) * ldc + cc]) = o;
            }
        }
    }
}

// ---------------- GEMM2: out (+)= scale*(act @ Wd); M=128 N=256 BK=16 --------
#define G2_CP(T_, BUF)                                                           \
    {                                                                            \
        const int _k0 = (T_) * 16;                                               \
        const size_t _bo = (size_t)_k0 * DM;                                     \
        uint32_t _d = smb + (BUF) * (G2_STAGE * 4);                              \
        CP16Z(_d + adst0 * 4, Asrc0 + _k0, asz0);                                \
        CP16Z(_d + adst1 * 4, Asrc1 + _k0, asz1);                                \
        _Pragma("unroll") for (int j = 0; j < 4; j++)                            \
            CP16(_d + (ASZ + bdst[j]) * 4, Bsrc[j] + _bo);                       \
    }

#define G2_COMP(BUF)                                                             \
    {                                                                            \
        const float* SA = sm + (BUF) * G2_STAGE;                                 \
        const float* SB = SA + ASZ;                                              \
        _Pragma("unroll") for (int kt = 0; kt < 2; kt++) {                       \
            const int ks = kt * 8;                                               \
            uint32_t a[4][4], b[8][2];                                           \
            _Pragma("unroll") for (int im = 0; im < 4; im++) {                   \
                const int m0 = wm_i * 64 + im * 16;                              \
                a[im][0] = au(SA[(m0 + grp) * ASTR + ks + tg]);                  \
                a[im][1] = au(SA[(m0 + 8 + grp) * ASTR + ks + tg]);              \
                a[im][2] = au(SA[(m0 + grp) * ASTR + ks + tg + 4]);              \
                a[im][3] = au(SA[(m0 + 8 + grp) * ASTR + ks + tg + 4]);          \
            }                                                                    \
            _Pragma("unroll") for (int in = 0; in < 8; in++) {                   \
                const int nb = wn_i * 64 + in * 8 + grp;                         \
                b[in][0] = au(SB[(ks + tg) * B2STR + nb]);                       \
                b[in][1] = au(SB[(ks + tg + 4) * B2STR + nb]);                   \
            }                                                                    \
            _Pragma("unroll") for (int im = 0; im < 4; im++)                     \
                _Pragma("unroll") for (int in = 0; in < 8; in++)                 \
                    mma8(c[im][in], a[im], b[in]);                               \
        }                                                                        \
    }

template <bool EXPERT>
__global__ __launch_bounds__(256, 1)
void gemm2_kernel(float* __restrict__ out) {
    extern __shared__ float sm[];
    const int e = EXPERT ? blockIdx.z : 0;
    const int M = EXPERT ? g_cnt[e] : NTOK;
    const int row0 = blockIdx.y * 128;
    if (row0 >= M) return;
    const int n0 = blockIdx.x * 256;
    const int K = EXPERT ? FE : FS;
    const float* Aact = EXPERT ? (g_acte + (size_t)e * NTOK * FE) : g_acts;
    const float* B = EXPERT ? (g_wd + (size_t)e * FE * DM) : g_wsd;
    const int* rl = g_list + e * NTOK;

    const int tid = threadIdx.x, l = tid & 31, w = tid >> 5;
    const uint32_t smb = smem_u32(sm);

    const int arow = tid >> 2, akq = tid & 3;
    const int adst0 = arow * ASTR + akq * 4;
    const int adst1 = (arow + 64) * ASTR + akq * 4;
    uint32_t asz0, asz1;
    const float* Asrc0;
    const float* Asrc1;
    {
        int r0 = row0 + arow, r1 = r0 + 64;
        asz0 = r0 < M ? 16u : 0u;
        asz1 = r1 < M ? 16u : 0u;
        Asrc0 = Aact + (size_t)(r0 < M ? r0 : 0) * K + akq * 4;
        Asrc1 = Aact + (size_t)(r1 < M ? r1 : 0) * K + akq * 4;
    }
    // B: 16 x 256 / 4 = 1024 chunks; 4 per thread: k rows tid>>6 + 4j, n-quad tid&63
    const int bk_ = tid >> 6, bnq = tid & 63;
    int bdst[4];
    const float* Bsrc[4];
#pragma unroll
    for (int j = 0; j < 4; j++) {
        int kk = bk_ + 4 * j;
        bdst[j] = kk * B2STR + bnq * 4;
        Bsrc[j] = B + (size_t)kk * DM + n0 + bnq * 4;
    }

    const int wm_i = w >> 2, wn_i = w & 3, grp = l >> 2, tg = l & 3;

    float c[4][8][4];
#pragma unroll
    for (int i = 0; i < 4; i++)
#pragma unroll
        for (int j = 0; j < 8; j++)
#pragma unroll
            for (int q = 0; q < 4; q++) c[i][j][q] = 0.f;

    const int T = K / 16;
    G2_CP(0, 0)
    CPCOMMIT();
    for (int t = 0; t < T; t++) {
        if (t + 1 < T) { G2_CP(t + 1, (t + 1) & 1) CPCOMMIT(); CPWAIT(1); }
        else CPWAIT(0);
        __syncthreads();
        G2_COMP(t & 1)
        __syncthreads();
    }

    // epilogue
#pragma unroll
    for (int im = 0; im < 4; im++) {
        int r = row0 + wm_i * 64 + im * 16 + grp;
        int tok0 = 0, tok1 = 0;
        float s0 = 0.f, s1 = 0.f;
        if (EXPERT) {
            if (r < M)     { tok0 = rl[r];     s0 = g_comb[tok0 * NE + e]; }
            if (r + 8 < M) { tok1 = rl[r + 8]; s1 = g_comb[tok1 * NE + e]; }
        } else {
            if (r < M)     s0 = g_sg[r];
            if (r + 8 < M) s1 = g_sg[r + 8];
        }
#pragma unroll
        for (int in = 0; in < 8; in++) {
            int cc = n0 + wn_i * 64 + in * 8 + 2 * tg;
            if (r < M) {
                if (EXPERT) {
                    atomicAdd(&out[(size_t)tok0 * DM + cc],     s0 * c[im][in][0]);
                    atomicAdd(&out[(size_t)tok0 * DM + cc + 1], s0 * c[im][in][1]);
                } else {
                    float2 o; o.x = s0 * c[im][in][0]; o.y = s0 * c[im][in][1];
                    *reinterpret_cast<float2*>(&out[(size_t)r * DM + cc]) = o;
                }
            }
            if (r + 8 < M) {
                if (EXPERT) {
                    atomicAdd(&out[(size_t)tok1 * DM + cc],     s1 * c[im][in][2]);
                    atomicAdd(&out[(size_t)tok1 * DM + cc + 1], s1 * c[im][in][3]);
                } else {
                    float2 o; o.x = s1 * c[im][in][2]; o.y = s1 * c[im][in][3];
                    *reinterpret_cast<float2*>(&out[(size_t)(r + 8) * DM + cc]) = o;
                }
            }
        }
    }
}

// ---------------- launch ----------------
extern "C" void kernel_launch(void* const* d_in, const int* in_sizes, int n_in,
                              void* d_out, int out_size) {
    const float* h       = (const float*)d_in[0];
    const float* gate_w  = (const float*)d_in[1];
    const float* w_gate  = (const float*)d_in[2];
    const float* w_up    = (const float*)d_in[3];
    const float* w_down  = (const float*)d_in[4];
    const float* ws_gate = (const float*)d_in[5];
    const float* ws_up   = (const float*)d_in[6];
    const float* ws_down = (const float*)d_in[7];
    const float* wsg     = (const float*)d_in[8];
    float* out = (float*)d_out;

    cudaFuncSetAttribute(gemm1_kernel<false>, cudaFuncAttributeMaxDynamicSharedMemorySize, SMEM_BYTES);
    cudaFuncSetAttribute(gemm1_kernel<true>,  cudaFuncAttributeMaxDynamicSharedMemorySize, SMEM_BYTES);
    cudaFuncSetAttribute(gemm2_kernel<false>, cudaFuncAttributeMaxDynamicSharedMemorySize, SMEM_BYTES);
    cudaFuncSetAttribute(gemm2_kernel<true>,  cudaFuncAttributeMaxDynamicSharedMemorySize, SMEM_BYTES);

    round_kernel<<<dim3(512, 7), 256>>>(h, w_gate, w_up, w_down, ws_gate, ws_up, ws_down);
    router_kernel<<<NTOK / 8, 256>>>(h, gate_w, wsg);
    build_lists_kernel<<<NE, 256>>>();

    gemm1_kernel<false><<<dim3(FS / 128, NTOK / 128), 256, SMEM_BYTES>>>();
    gemm1_kernel<true><<<dim3(FE / 128, NTOK / 128, NE), 256, SMEM_BYTES>>>();
    gemm2_kernel<false><<<dim3(DM / 256, NTOK / 128), 256, SMEM_BYTES>>>(out);
    gemm2_kernel<true><<<dim3(DM / 256, NTOK / 128, NE), 256, SMEM_BYTES>>>(out);
}

// round 8
// speedup vs baseline: 2.2995x; 1.1068x over previous
#include <cuda_runtime.h>
#include <stdint.h>

#define NTOK 8192
#define DM   2048
#define NE   8
#define FE   1024
#define FS   2048

// ---------------- scratch (device globals; no allocation) ----------------
__device__ float g_comb[NTOK * NE];
__device__ float g_sg[NTOK];
__device__ int   g_top[NTOK * 2];
__device__ int   g_cnt[NE];
__device__ int   g_list[NE * NTOK];
__device__ float g_acte[(size_t)NE * NTOK * FE];   // per-expert act (compact rows, tf32-rounded)
__device__ float g_acts[(size_t)NTOK * FS];        // shared-expert act (tf32-rounded)
__device__ float g_ht[(size_t)NTOK * DM];          // tf32-rounded h
// tf32-rounded weights, ORIGINAL layouts
__device__ float g_wg[(size_t)NE * DM * FE];
__device__ float g_wu[(size_t)NE * DM * FE];
__device__ float g_wd[(size_t)NE * FE * DM];
__device__ float g_wsg2[(size_t)DM * FS];
__device__ float g_wsu[(size_t)DM * FS];
__device__ float g_wsd[(size_t)FS * DM];

// ---------------- helpers ----------------
__device__ __forceinline__ uint32_t f2tf(float x) {
    uint32_t r;
    asm("cvt.rna.tf32.f32 %0, %1;" : "=r"(r) : "f"(x));
    return r;
}
__device__ __forceinline__ float tf32r(float x) { return __uint_as_float(f2tf(x)); }
__device__ __forceinline__ uint32_t au(float x) { return __float_as_uint(x); }
__device__ __forceinline__ uint32_t smem_u32(const void* p) {
    uint32_t a;
    asm("{ .reg .u64 t; cvta.to.shared.u64 t, %1; cvt.u32.u64 %0, t; }" : "=r"(a) : "l"(p));
    return a;
}

__device__ __forceinline__ void mma8(float* c, const uint32_t* a, const uint32_t* b) {
    asm volatile(
        "mma.sync.aligned.m16n8k8.row.col.f32.tf32.tf32.f32 "
        "{%0,%1,%2,%3},{%4,%5,%6,%7},{%8,%9},{%0,%1,%2,%3};"
        : "+f"(c[0]), "+f"(c[1]), "+f"(c[2]), "+f"(c[3])
        : "r"(a[0]), "r"(a[1]), "r"(a[2]), "r"(a[3]), "r"(b[0]), "r"(b[1]));
}

#define CP16(dst, src) \
    asm volatile("cp.async.cg.shared.global [%0], [%1], 16;" :: "r"(dst), "l"(src) : "memory")
#define CP16Z(dst, src, sz) \
    asm volatile("cp.async.cg.shared.global [%0], [%1], 16, %2;" :: "r"(dst), "l"(src), "r"(sz) : "memory")
#define CPCOMMIT() asm volatile("cp.async.commit_group;" ::: "memory")
#define CPWAIT(n)  asm volatile("cp.async.wait_group %0;" :: "n"(n) : "memory")

// ---------------- prep: tf32-round inputs/weights (layout preserved) ----------------
__global__ void round_kernel(const float* __restrict__ h, const float* __restrict__ w_gate,
                             const float* __restrict__ w_up, const float* __restrict__ w_down,
                             const float* __restrict__ ws_gate, const float* __restrict__ ws_up,
                             const float* __restrict__ ws_down) {
    int which = blockIdx.y;
    const float* in; float* out; size_t n;
    switch (which) {
        case 0: in = h;       out = g_ht;   n = (size_t)NTOK * DM;     break;
        case 1: in = w_gate;  out = g_wg;   n = (size_t)NE * DM * FE;  break;
        case 2: in = w_up;    out = g_wu;   n = (size_t)NE * DM * FE;  break;
        case 3: in = w_down;  out = g_wd;   n = (size_t)NE * FE * DM;  break;
        case 4: in = ws_gate; out = g_wsg2; n = (size_t)DM * FS;       break;
        case 5: in = ws_up;   out = g_wsu;  n = (size_t)DM * FS;       break;
        default:in = ws_down; out = g_wsd;  n = (size_t)FS * DM;       break;
    }
    size_t n4 = n >> 2;
    for (size_t i = (size_t)blockIdx.x * blockDim.x + threadIdx.x; i < n4;
         i += (size_t)gridDim.x * blockDim.x) {
        float4 v = reinterpret_cast<const float4*>(in)[i];
        v.x = tf32r(v.x); v.y = tf32r(v.y); v.z = tf32r(v.z); v.w = tf32r(v.w);
        reinterpret_cast<float4*>(out)[i] = v;
    }
}

// ---------------- router ----------------
__global__ void router_kernel(const float* __restrict__ h,
                              const float* __restrict__ gw,
                              const float* __restrict__ wsg) {
    int lane = threadIdx.x & 31;
    int t = blockIdx.x * (blockDim.x >> 5) + (threadIdx.x >> 5);
    if (t >= NTOK) return;
    const float* hr = h + (size_t)t * DM;
    float acc[8];
#pragma unroll
    for (int i = 0; i < 8; i++) acc[i] = 0.f;
    float as_ = 0.f;
    for (int d = lane; d < DM; d += 32) {
        float hv = hr[d];
        const float4* gr = reinterpret_cast<const float4*>(gw + (size_t)d * NE);
        float4 g0 = gr[0], g1 = gr[1];
        acc[0] += hv * g0.x; acc[1] += hv * g0.y; acc[2] += hv * g0.z; acc[3] += hv * g0.w;
        acc[4] += hv * g1.x; acc[5] += hv * g1.y; acc[6] += hv * g1.z; acc[7] += hv * g1.w;
        as_ += hv * wsg[d];
    }
#pragma unroll
    for (int o = 16; o; o >>= 1) {
#pragma unroll
        for (int i = 0; i < 8; i++) acc[i] += __shfl_xor_sync(0xffffffffu, acc[i], o);
        as_ += __shfl_xor_sync(0xffffffffu, as_, o);
    }
    if (lane == 0) {
        int i1 = 0;
#pragma unroll
        for (int e = 1; e < 8; e++) if (acc[e] > acc[i1]) i1 = e;
        int i2 = -1;
#pragma unroll
        for (int e = 0; e < 8; e++) {
            if (e == i1) continue;
            if (i2 < 0 || acc[e] > acc[i2]) i2 = e;
        }
        float e2 = __expf(acc[i2] - acc[i1]);
        float w1 = 1.f / (1.f + e2);
        float w2 = e2 / (1.f + e2);
#pragma unroll
        for (int e = 0; e < 8; e++)
            g_comb[t * NE + e] = (e == i1) ? w1 : ((e == i2) ? w2 : 0.f);
        g_top[t * 2] = i1;
        g_top[t * 2 + 1] = i2;
        g_sg[t] = 1.f / (1.f + __expf(-as_));
    }
}

__global__ void build_lists_kernel() {
    int e = blockIdx.x;
    int tid = threadIdx.x;
    __shared__ int warp_cnt[8];
    __shared__ int s_base;
    if (tid == 0) s_base = 0;
    __syncthreads();
    for (int base = 0; base < NTOK; base += 256) {
        int t = base + tid;
        int flag = (g_top[t * 2] == e) || (g_top[t * 2 + 1] == e);
        unsigned bal = __ballot_sync(0xffffffffu, flag);
        int lane = tid & 31, w = tid >> 5;
        if (lane == 0) warp_cnt[w] = __popc(bal);
        __syncthreads();
        int off = 0;
        for (int i = 0; i < w; i++) off += warp_cnt[i];
        int pos = s_base + off + __popc(bal & ((1u << lane) - 1u));
        if (flag) g_list[e * NTOK + pos] = t;
        __syncthreads();
        if (tid == 0) {
            int tot = 0;
            for (int i = 0; i < 8; i++) tot += warp_cnt[i];
            s_base += tot;
        }
        __syncthreads();
    }
    if (tid == 0) g_cnt[e] = s_base;
}

// =====================================================================
// SMEM layouts (floats), BK = 32, 3-stage ring:
//  A : [m 0..127][k 0..31], row stride 36 words (144B).
//      Fragment bank = (4*grp + tg) mod 32 -> conflict-free.
//  B : [k 0..31][n], row stride 136 (BN=128) / 264 (BN=256), ==8 mod 32.
//      Fragment bank = (8*tg + grp) mod 32 -> conflict-free.
// =====================================================================
#define ASTR   36
#define ASZ    (128 * ASTR)          // 4608 words
#define B1STR  136
#define B1SZ   (32 * B1STR)          // 4352 words
#define B2STR  264
#define B2SZ   (32 * B2STR)          // 8448 words
#define G1_STAGE (ASZ + 2 * B1SZ)    // 13312 words (53248 B)
#define G2_STAGE (ASZ + B2SZ)        // 13056 words (52224 B)
#define G1_SMEM (3 * G1_STAGE * 4)   // 159744 B
#define G2_SMEM (3 * G2_STAGE * 4)   // 156672 B

// ---------------- GEMM1: act = silu(X@Wg)*(X@Wu); M=128 N=128 BK=32 ----------
#define G1_CP(T_, BUF)                                                           \
    {                                                                            \
        const int _k0 = (T_) * 32;                                               \
        const size_t _bo = (size_t)_k0 * ldb;                                    \
        uint32_t _d = smb + (BUF) * (G1_STAGE * 4);                              \
        _Pragma("unroll") for (int p = 0; p < 4; p++)                            \
            CP16Z(_d + adst[p] * 4, Asrc[p] + _k0, asz[p]);                      \
        _Pragma("unroll") for (int j = 0; j < 4; j++) {                          \
            CP16(_d + (ASZ + bdst[j]) * 4, Bsrc1[j] + _bo);                      \
            CP16(_d + (ASZ + B1SZ + bdst[j]) * 4, Bsrc2[j] + _bo);               \
        }                                                                        \
    }

#define G1_COMP(BUF)                                                             \
    {                                                                            \
        const float* SA = sm + (BUF) * G1_STAGE;                                 \
        const float* SB1 = SA + ASZ;                                             \
        const float* SB2 = SB1 + B1SZ;                                           \
        _Pragma("unroll") for (int kt = 0; kt < 4; kt++) {                       \
            const int ks = kt * 8;                                               \
            uint32_t a[4][4], b1[4][2], b2[4][2];                                \
            _Pragma("unroll") for (int im = 0; im < 4; im++) {                   \
                const int m0 = wm_i * 64 + im * 16;                              \
                a[im][0] = au(SA[(m0 + grp) * ASTR + ks + tg]);                  \
                a[im][1] = au(SA[(m0 + 8 + grp) * ASTR + ks + tg]);              \
                a[im][2] = au(SA[(m0 + grp) * ASTR + ks + tg + 4]);              \
                a[im][3] = au(SA[(m0 + 8 + grp) * ASTR + ks + tg + 4]);          \
            }                                                                    \
            _Pragma("unroll") for (int in = 0; in < 4; in++) {                   \
                const int nb = wn_i * 32 + in * 8 + grp;                         \
                b1[in][0] = au(SB1[(ks + tg) * B1STR + nb]);                     \
                b1[in][1] = au(SB1[(ks + tg + 4) * B1STR + nb]);                 \
                b2[in][0] = au(SB2[(ks + tg) * B1STR + nb]);                     \
                b2[in][1] = au(SB2[(ks + tg + 4) * B1STR + nb]);                 \
            }                                                                    \
            _Pragma("unroll") for (int im = 0; im < 4; im++)                     \
                _Pragma("unroll") for (int in = 0; in < 4; in++) {               \
                    mma8(c1[im][in], a[im], b1[in]);                             \
                    mma8(c2[im][in], a[im], b2[in]);                             \
                }                                                                \
        }                                                                        \
    }

template <bool EXPERT>
__global__ __launch_bounds__(256, 1)
void gemm1_kernel() {
    extern __shared__ float sm[];
    const int e = EXPERT ? blockIdx.z : 0;
    const int M = EXPERT ? g_cnt[e] : NTOK;
    const int row0 = blockIdx.y * 128;
    if (row0 >= M) return;
    const int n0 = blockIdx.x * 128;
    const int ldb = EXPERT ? FE : FS;
    const float* B1 = EXPERT ? (g_wg + (size_t)e * DM * FE) : g_wsg2;
    const float* B2 = EXPERT ? (g_wu + (size_t)e * DM * FE) : g_wsu;
    float* C = EXPERT ? (g_acte + (size_t)e * NTOK * FE) : g_acts;
    const int* rl = g_list + e * NTOK;

    const int tid = threadIdx.x, l = tid & 31, w = tid >> 5;
    const uint32_t smb = smem_u32(sm);

    // --- staging maps ---
    // A: 128 rows x 32 k = 1024 16B chunks; thread -> rows (tid>>3)+32p, k-oct tid&7
    const int arow = tid >> 3, akq = tid & 7;
    int adst[4];
    uint32_t asz[4];
    const float* Asrc[4];
#pragma unroll
    for (int p = 0; p < 4; p++) {
        int rloc = arow + 32 * p;
        adst[p] = rloc * ASTR + akq * 4;
        int r = row0 + rloc;
        asz[p] = r < M ? 16u : 0u;
        int s = r < M ? (EXPERT ? rl[r] : r) : 0;
        Asrc[p] = g_ht + (size_t)s * DM + akq * 4;
    }
    // B: 32 rows x 128 n = 1024 chunks per matrix; thread -> k rows (tid>>5)+8j, n-quad tid&31
    const int bk_ = tid >> 5, bnq = tid & 31;
    int bdst[4];
    const float* Bsrc1[4];
    const float* Bsrc2[4];
#pragma unroll
    for (int j = 0; j < 4; j++) {
        int kk = bk_ + 8 * j;
        bdst[j] = kk * B1STR + bnq * 4;
        Bsrc1[j] = B1 + (size_t)kk * ldb + n0 + bnq * 4;
        Bsrc2[j] = B2 + (size_t)kk * ldb + n0 + bnq * 4;
    }

    // --- compute maps ---
    const int wm_i = w >> 2, wn_i = w & 3, grp = l >> 2, tg = l & 3;

    float c1[4][4][4], c2[4][4][4];
#pragma unroll
    for (int i = 0; i < 4; i++)
#pragma unroll
        for (int j = 0; j < 4; j++)
#pragma unroll
            for (int q = 0; q < 4; q++) { c1[i][j][q] = 0.f; c2[i][j][q] = 0.f; }

    const int T = DM / 32;
    G1_CP(0, 0) CPCOMMIT();
    G1_CP(1, 1) CPCOMMIT();
    int buf = 0, nbuf = 2;
    for (int t = 0; t < T; t++) {
        CPWAIT(1);
        __syncthreads();
        if (t + 2 < T) G1_CP(t + 2, nbuf)
        CPCOMMIT();
        G1_COMP(buf)
        buf = buf == 2 ? 0 : buf + 1;
        nbuf = nbuf == 2 ? 0 : nbuf + 1;
    }

    // epilogue: silu(gate)*up, rounded to tf32 (so gemm2 can stage raw)
    const int ldc = ldb;
#pragma unroll
    for (int im = 0; im < 4; im++) {
        int r = row0 + wm_i * 64 + im * 16 + grp;
#pragma unroll
        for (int in = 0; in < 4; in++) {
            int cc = n0 + wn_i * 32 + in * 8 + 2 * tg;
            if (r < M) {
                float g0 = c1[im][in][0], u0 = c2[im][in][0];
                float g1 = c1[im][in][1], u1 = c2[im][in][1];
                float2 o;
                o.x = tf32r(g0 * (1.f / (1.f + __expf(-g0))) * u0);
                o.y = tf32r(g1 * (1.f / (1.f + __expf(-g1))) * u1);
                *reinterpret_cast<float2*>(&C[(size_t)r * ldc + cc]) = o;
            }
            if (r + 8 < M) {
                float g0 = c1[im][in][2], u0 = c2[im][in][2];
                float g1 = c1[im][in][3], u1 = c2[im][in][3];
                float2 o;
                o.x = tf32r(g0 * (1.f / (1.f + __expf(-g0))) * u0);
                o.y = tf32r(g1 * (1.f / (1.f + __expf(-g1))) * u1);
                *reinterpret_cast<float2*>(&C[(size_t)(r + 8) * ldc + cc]) = o;
            }
        }
    }
}

// ---------------- GEMM2: out (+)= scale*(act @ Wd); M=128 N=256 BK=32 --------
#define G2_CP(T_, BUF)                                                           \
    {                                                                            \
        const int _k0 = (T_) * 32;                                               \
        const size_t _bo = (size_t)_k0 * DM;                                     \
        uint32_t _d = smb + (BUF) * (G2_STAGE * 4);                              \
        _Pragma("unroll") for (int p = 0; p < 4; p++)                            \
            CP16Z(_d + adst[p] * 4, Asrc[p] + _k0, asz[p]);                      \
        _Pragma("unroll") for (int j = 0; j < 8; j++)                            \
            CP16(_d + (ASZ + bdst[j]) * 4, Bsrc[j] + _bo);                       \
    }

#define G2_COMP(BUF)                                                             \
    {                                                                            \
        const float* SA = sm + (BUF) * G2_STAGE;                                 \
        const float* SB = SA + ASZ;                                              \
        _Pragma("unroll") for (int kt = 0; kt < 4; kt++) {                       \
            const int ks = kt * 8;                                               \
            uint32_t a[4][4], b[8][2];                                           \
            _Pragma("unroll") for (int im = 0; im < 4; im++) {                   \
                const int m0 = wm_i * 64 + im * 16;                              \
                a[im][0] = au(SA[(m0 + grp) * ASTR + ks + tg]);                  \
                a[im][1] = au(SA[(m0 + 8 + grp) * ASTR + ks + tg]);              \
                a[im][2] = au(SA[(m0 + grp) * ASTR + ks + tg + 4]);              \
                a[im][3] = au(SA[(m0 + 8 + grp) * ASTR + ks + tg + 4]);          \
            }                                                                    \
            _Pragma("unroll") for (int in = 0; in < 8; in++) {                   \
                const int nb = wn_i * 64 + in * 8 + grp;                         \
                b[in][0] = au(SB[(ks + tg) * B2STR + nb]);                       \
                b[in][1] = au(SB[(ks + tg + 4) * B2STR + nb]);                   \
            }                                                                    \
            _Pragma("unroll") for (int im = 0; im < 4; im++)                     \
                _Pragma("unroll") for (int in = 0; in < 8; in++)                 \
                    mma8(c[im][in], a[im], b[in]);                               \
        }                                                                        \
    }

template <bool EXPERT>
__global__ __launch_bounds__(256, 1)
void gemm2_kernel(float* __restrict__ out) {
    extern __shared__ float sm[];
    const int e = EXPERT ? blockIdx.z : 0;
    const int M = EXPERT ? g_cnt[e] : NTOK;
    const int row0 = blockIdx.y * 128;
    if (row0 >= M) return;
    const int n0 = blockIdx.x * 256;
    const int K = EXPERT ? FE : FS;
    const float* Aact = EXPERT ? (g_acte + (size_t)e * NTOK * FE) : g_acts;
    const float* B = EXPERT ? (g_wd + (size_t)e * FE * DM) : g_wsd;
    const int* rl = g_list + e * NTOK;

    const int tid = threadIdx.x, l = tid & 31, w = tid >> 5;
    const uint32_t smb = smem_u32(sm);

    const int arow = tid >> 3, akq = tid & 7;
    int adst[4];
    uint32_t asz[4];
    const float* Asrc[4];
#pragma unroll
    for (int p = 0; p < 4; p++) {
        int rloc = arow + 32 * p;
        adst[p] = rloc * ASTR + akq * 4;
        int r = row0 + rloc;
        asz[p] = r < M ? 16u : 0u;
        Asrc[p] = Aact + (size_t)(r < M ? r : 0) * K + akq * 4;
    }
    // B: 32 rows x 256 n = 2048 chunks; thread -> k rows (tid>>6)+4j, n-quad tid&63
    const int bk_ = tid >> 6, bnq = tid & 63;
    int bdst[8];
    const float* Bsrc[8];
#pragma unroll
    for (int j = 0; j < 8; j++) {
        int kk = bk_ + 4 * j;
        bdst[j] = kk * B2STR + bnq * 4;
        Bsrc[j] = B + (size_t)kk * DM + n0 + bnq * 4;
    }

    const int wm_i = w >> 2, wn_i = w & 3, grp = l >> 2, tg = l & 3;

    float c[4][8][4];
#pragma unroll
    for (int i = 0; i < 4; i++)
#pragma unroll
        for (int j = 0; j < 8; j++)
#pragma unroll
            for (int q = 0; q < 4; q++) c[i][j][q] = 0.f;

    const int T = K / 32;
    G2_CP(0, 0) CPCOMMIT();
    G2_CP(1, 1) CPCOMMIT();
    int buf = 0, nbuf = 2;
    for (int t = 0; t < T; t++) {
        CPWAIT(1);
        __syncthreads();
        if (t + 2 < T) G2_CP(t + 2, nbuf)
        CPCOMMIT();
        G2_COMP(buf)
        buf = buf == 2 ? 0 : buf + 1;
        nbuf = nbuf == 2 ? 0 : nbuf + 1;
    }

    // epilogue
#pragma unroll
    for (int im = 0; im < 4; im++) {
        int r = row0 + wm_i * 64 + im * 16 + grp;
        int tok0 = 0, tok1 = 0;
        float s0 = 0.f, s1 = 0.f;
        if (EXPERT) {
            if (r < M)     { tok0 = rl[r];     s0 = g_comb[tok0 * NE + e]; }
            if (r + 8 < M) { tok1 = rl[r + 8]; s1 = g_comb[tok1 * NE + e]; }
        } else {
            if (r < M)     s0 = g_sg[r];
            if (r + 8 < M) s1 = g_sg[r + 8];
        }
#pragma unroll
        for (int in = 0; in < 8; in++) {
            int cc = n0 + wn_i * 64 + in * 8 + 2 * tg;
            if (r < M) {
                if (EXPERT) {
                    atomicAdd(&out[(size_t)tok0 * DM + cc],     s0 * c[im][in][0]);
                    atomicAdd(&out[(size_t)tok0 * DM + cc + 1], s0 * c[im][in][1]);
                } else {
                    float2 o; o.x = s0 * c[im][in][0]; o.y = s0 * c[im][in][1];
                    *reinterpret_cast<float2*>(&out[(size_t)r * DM + cc]) = o;
                }
            }
            if (r + 8 < M) {
                if (EXPERT) {
                    atomicAdd(&out[(size_t)tok1 * DM + cc],     s1 * c[im][in][2]);
                    atomicAdd(&out[(size_t)tok1 * DM + cc + 1], s1 * c[im][in][3]);
                } else {
                    float2 o; o.x = s1 * c[im][in][2]; o.y = s1 * c[im][in][3];
                    *reinterpret_cast<float2*>(&out[(size_t)(r + 8) * DM + cc]) = o;
                }
            }
        }
    }
}

// ---------------- launch ----------------
extern "C" void kernel_launch(void* const* d_in, const int* in_sizes, int n_in,
                              void* d_out, int out_size) {
    const float* h       = (const float*)d_in[0];
    const float* gate_w  = (const float*)d_in[1];
    const float* w_gate  = (const float*)d_in[2];
    const float* w_up    = (const float*)d_in[3];
    const float* w_down  = (const float*)d_in[4];
    const float* ws_gate = (const float*)d_in[5];
    const float* ws_up   = (const float*)d_in[6];
    const float* ws_down = (const float*)d_in[7];
    const float* wsg     = (const float*)d_in[8];
    float* out = (float*)d_out;

    cudaFuncSetAttribute(gemm1_kernel<false>, cudaFuncAttributeMaxDynamicSharedMemorySize, G1_SMEM);
    cudaFuncSetAttribute(gemm1_kernel<true>,  cudaFuncAttributeMaxDynamicSharedMemorySize, G1_SMEM);
    cudaFuncSetAttribute(gemm2_kernel<false>, cudaFuncAttributeMaxDynamicSharedMemorySize, G2_SMEM);
    cudaFuncSetAttribute(gemm2_kernel<true>,  cudaFuncAttributeMaxDynamicSharedMemorySize, G2_SMEM);

    round_kernel<<<dim3(512, 7), 256>>>(h, w_gate, w_up, w_down, ws_gate, ws_up, ws_down);
    router_kernel<<<NTOK / 8, 256>>>(h, gate_w, wsg);
    build_lists_kernel<<<NE, 256>>>();

    gemm1_kernel<false><<<dim3(FS / 128, NTOK / 128), 256, G1_SMEM>>>();
    gemm1_kernel<true><<<dim3(FE / 128, NTOK / 128, NE), 256, G1_SMEM>>>();
    gemm2_kernel<false><<<dim3(DM / 256, NTOK / 128), 256, G2_SMEM>>>(out);
    gemm2_kernel<true><<<dim3(DM / 256, NTOK / 128, NE), 256, G2_SMEM>>>(out);
}

// round 10
// speedup vs baseline: 2.3147x; 1.0066x over previous
#include <cuda_runtime.h>
#include <stdint.h>

#define NTOK 8192
#define DM   2048
#define NE   8
#define FE   1024
#define FS   2048

// ---------------- scratch (device globals; no allocation) ----------------
__device__ float g_wt[NTOK * 2];        // normalized top-2 weights (slot order)
__device__ int   g_rowidx[NTOK * 2];    // token -> global compact row (e*NTOK+pos)
__device__ float g_sg[NTOK];
__device__ int   g_top[NTOK * 2];
__device__ int   g_cnt[NE];
__device__ int   g_list[NE * NTOK];
__device__ float g_acte[(size_t)NE * NTOK * FE];   // per-expert act (compact rows)
__device__ float g_acts[(size_t)NTOK * FS];        // shared-expert act
__device__ float g_eout[(size_t)NE * NTOK * DM];   // expert down-proj (compact rows)
__device__ float g_ht[(size_t)NTOK * DM];          // tf32-rounded h
// tf32-rounded weights, ORIGINAL layouts
__device__ float g_wg[(size_t)NE * DM * FE];
__device__ float g_wu[(size_t)NE * DM * FE];
__device__ float g_wd[(size_t)NE * FE * DM];
__device__ float g_wsg2[(size_t)DM * FS];
__device__ float g_wsu[(size_t)DM * FS];
__device__ float g_wsd[(size_t)FS * DM];

// ---------------- helpers ----------------
__device__ __forceinline__ uint32_t f2tf(float x) {
    uint32_t r;
    asm("cvt.rna.tf32.f32 %0, %1;" : "=r"(r) : "f"(x));
    return r;
}
__device__ __forceinline__ float tf32r(float x) { return __uint_as_float(f2tf(x)); }
__device__ __forceinline__ uint32_t au(float x) { return __float_as_uint(x); }
__device__ __forceinline__ uint32_t smem_u32(const void* p) {
    uint32_t a;
    asm("{ .reg .u64 t; cvta.to.shared.u64 t, %1; cvt.u32.u64 %0, t; }" : "=r"(a) : "l"(p));
    return a;
}

__device__ __forceinline__ void mma8(float* c, const uint32_t* a, const uint32_t* b) {
    asm volatile(
        "mma.sync.aligned.m16n8k8.row.col.f32.tf32.tf32.f32 "
        "{%0,%1,%2,%3},{%4,%5,%6,%7},{%8,%9},{%0,%1,%2,%3};"
        : "+f"(c[0]), "+f"(c[1]), "+f"(c[2]), "+f"(c[3])
        : "r"(a[0]), "r"(a[1]), "r"(a[2]), "r"(a[3]), "r"(b[0]), "r"(b[1]));
}

#define CP16(dst, src) \
    asm volatile("cp.async.cg.shared.global [%0], [%1], 16;" :: "r"(dst), "l"(src) : "memory")
#define CP16Z(dst, src, sz) \
    asm volatile("cp.async.cg.shared.global [%0], [%1], 16, %2;" :: "r"(dst), "l"(src), "r"(sz) : "memory")
#define CPCOMMIT() asm volatile("cp.async.commit_group;" ::: "memory")
#define CPWAIT(n)  asm volatile("cp.async.wait_group %0;" :: "n"(n) : "memory")

// ---------------- prep: tf32-round inputs/weights (layout preserved) ----------------
__global__ void round_kernel(const float* __restrict__ h, const float* __restrict__ w_gate,
                             const float* __restrict__ w_up, const float* __restrict__ w_down,
                             const float* __restrict__ ws_gate, const float* __restrict__ ws_up,
                             const float* __restrict__ ws_down) {
    int which = blockIdx.y;
    const float* in; float* out; size_t n;
    switch (which) {
        case 0: in = h;       out = g_ht;   n = (size_t)NTOK * DM;     break;
        case 1: in = w_gate;  out = g_wg;   n = (size_t)NE * DM * FE;  break;
        case 2: in = w_up;    out = g_wu;   n = (size_t)NE * DM * FE;  break;
        case 3: in = w_down;  out = g_wd;   n = (size_t)NE * FE * DM;  break;
        case 4: in = ws_gate; out = g_wsg2; n = (size_t)DM * FS;       break;
        case 5: in = ws_up;   out = g_wsu;  n = (size_t)DM * FS;       break;
        default:in = ws_down; out = g_wsd;  n = (size_t)FS * DM;       break;
    }
    size_t n4 = n >> 2;
    for (size_t i = (size_t)blockIdx.x * blockDim.x + threadIdx.x; i < n4;
         i += (size_t)gridDim.x * blockDim.x) {
        float4 v = reinterpret_cast<const float4*>(in)[i];
        v.x = tf32r(v.x); v.y = tf32r(v.y); v.z = tf32r(v.z); v.w = tf32r(v.w);
        reinterpret_cast<float4*>(out)[i] = v;
    }
}

// ---------------- router ----------------
__global__ void router_kernel(const float* __restrict__ h,
                              const float* __restrict__ gw,
                              const float* __restrict__ wsg) {
    int lane = threadIdx.x & 31;
    int t = blockIdx.x * (blockDim.x >> 5) + (threadIdx.x >> 5);
    if (t >= NTOK) return;
    const float* hr = h + (size_t)t * DM;
    float acc[8];
#pragma unroll
    for (int i = 0; i < 8; i++) acc[i] = 0.f;
    float as_ = 0.f;
    for (int d = lane; d < DM; d += 32) {
        float hv = hr[d];
        const float4* gr = reinterpret_cast<const float4*>(gw + (size_t)d * NE);
        float4 g0 = gr[0], g1 = gr[1];
        acc[0] += hv * g0.x; acc[1] += hv * g0.y; acc[2] += hv * g0.z; acc[3] += hv * g0.w;
        acc[4] += hv * g1.x; acc[5] += hv * g1.y; acc[6] += hv * g1.z; acc[7] += hv * g1.w;
        as_ += hv * wsg[d];
    }
#pragma unroll
    for (int o = 16; o; o >>= 1) {
#pragma unroll
        for (int i = 0; i < 8; i++) acc[i] += __shfl_xor_sync(0xffffffffu, acc[i], o);
        as_ += __shfl_xor_sync(0xffffffffu, as_, o);
    }
    if (lane == 0) {
        int i1 = 0;
#pragma unroll
        for (int e = 1; e < 8; e++) if (acc[e] > acc[i1]) i1 = e;
        int i2 = -1;
#pragma unroll
        for (int e = 0; e < 8; e++) {
            if (e == i1) continue;
            if (i2 < 0 || acc[e] > acc[i2]) i2 = e;
        }
        float e2 = __expf(acc[i2] - acc[i1]);
        float w1 = 1.f / (1.f + e2);
        float w2 = e2 / (1.f + e2);
        g_wt[t * 2] = w1;
        g_wt[t * 2 + 1] = w2;
        g_top[t * 2] = i1;
        g_top[t * 2 + 1] = i2;
        g_sg[t] = 1.f / (1.f + __expf(-as_));
    }
}

__global__ void build_lists_kernel() {
    int e = blockIdx.x;
    int tid = threadIdx.x;
    __shared__ int warp_cnt[8];
    __shared__ int s_base;
    if (tid == 0) s_base = 0;
    __syncthreads();
    for (int base = 0; base < NTOK; base += 256) {
        int t = base + tid;
        int top0 = g_top[t * 2], top1 = g_top[t * 2 + 1];
        int flag = (top0 == e) || (top1 == e);
        unsigned bal = __ballot_sync(0xffffffffu, flag);
        int lane = tid & 31, w = tid >> 5;
        if (lane == 0) warp_cnt[w] = __popc(bal);
        __syncthreads();
        int off = 0;
        for (int i = 0; i < w; i++) off += warp_cnt[i];
        int pos = s_base + off + __popc(bal & ((1u << lane) - 1u));
        if (flag) {
            g_list[e * NTOK + pos] = t;
            int slot = (top0 == e) ? 0 : 1;
            g_rowidx[t * 2 + slot] = e * NTOK + pos;
        }
        __syncthreads();
        if (tid == 0) {
            int tot = 0;
            for (int i = 0; i < 8; i++) tot += warp_cnt[i];
            s_base += tot;
        }
        __syncthreads();
    }
    if (tid == 0) g_cnt[e] = s_base;
}

// =====================================================================
// SMEM layouts (floats), BK = 64, 2-stage:
//  A : [m 0..127][k 0..63], row stride 68 words. Fragment reads conflict-free.
//  B : [k 0..63][n], row stride 136 (BN=128) / 264 (BN=256), ==8 mod 32. CF.
// =====================================================================
#define ASTR   68
#define ASZ    (128 * ASTR)          // 8704 words
#define B1STR  136
#define B1SZ   (64 * B1STR)          // 8704 words
#define B2STR  264
#define B2SZ   (64 * B2STR)          // 16896 words
#define G1_STAGE (ASZ + 2 * B1SZ)    // 26112 words (104448 B)
#define G2_STAGE (ASZ + B2SZ)        // 25600 words (102400 B)
#define G1_SMEM (2 * G1_STAGE * 4)   // 208896 B
#define G2_SMEM (2 * G2_STAGE * 4)   // 204800 B

// ---------------- GEMM1: act = silu(X@Wg)*(X@Wu); M=128 N=128 BK=64 ----------
#define G1_CP(T_, BUF)                                                           \
    {                                                                            \
        const int _k0 = (T_) * 64;                                               \
        const size_t _bo = (size_t)_k0 * ldb;                                    \
        uint32_t _d = smb + (BUF) * (G1_STAGE * 4);                              \
        _Pragma("unroll") for (int p = 0; p < 8; p++)                            \
            CP16Z(_d + adst[p] * 4, Asrc[p] + _k0, asz[p]);                      \
        _Pragma("unroll") for (int j = 0; j < 8; j++) {                          \
            CP16(_d + (ASZ + bdst[j]) * 4, Bsrc1[j] + _bo);                      \
            CP16(_d + (ASZ + B1SZ + bdst[j]) * 4, Bsrc2[j] + _bo);               \
        }                                                                        \
    }

#define G1_COMP(BUF)                                                             \
    {                                                                            \
        const float* SA = sm + (BUF) * G1_STAGE;                                 \
        const float* SB1 = SA + ASZ;                                             \
        const float* SB2 = SB1 + B1SZ;                                           \
        _Pragma("unroll") for (int kt = 0; kt < 8; kt++) {                       \
            const int ks = kt * 8;                                               \
            uint32_t a[4][4], b1[4][2], b2[4][2];                                \
            _Pragma("unroll") for (int im = 0; im < 4; im++) {                   \
                const int m0 = wm_i * 64 + im * 16;                              \
                a[im][0] = au(SA[(m0 + grp) * ASTR + ks + tg]);                  \
                a[im][1] = au(SA[(m0 + 8 + grp) * ASTR + ks + tg]);              \
                a[im][2] = au(SA[(m0 + grp) * ASTR + ks + tg + 4]);              \
                a[im][3] = au(SA[(m0 + 8 + grp) * ASTR + ks + tg + 4]);          \
            }                                                                    \
            _Pragma("unroll") for (int in = 0; in < 4; in++) {                   \
                const int nb = wn_i * 32 + in * 8 + grp;                         \
                b1[in][0] = au(SB1[(ks + tg) * B1STR + nb]);                     \
                b1[in][1] = au(SB1[(ks + tg + 4) * B1STR + nb]);                 \
                b2[in][0] = au(SB2[(ks + tg) * B1STR + nb]);                     \
                b2[in][1] = au(SB2[(ks + tg + 4) * B1STR + nb]);                 \
            }                                                                    \
            _Pragma("unroll") for (int im = 0; im < 4; im++)                     \
                _Pragma("unroll") for (int in = 0; in < 4; in++) {               \
                    mma8(c1[im][in], a[im], b1[in]);                             \
                    mma8(c2[im][in], a[im], b2[in]);                             \
                }                                                                \
        }                                                                        \
    }

template <bool EXPERT>
__global__ __launch_bounds__(256, 1)
void gemm1_kernel() {
    extern __shared__ float sm[];
    const int e = EXPERT ? blockIdx.z : 0;
    const int M = EXPERT ? g_cnt[e] : NTOK;
    const int row0 = blockIdx.y * 128;
    if (row0 >= M) return;
    const int n0 = blockIdx.x * 128;
    const int ldb = EXPERT ? FE : FS;
    const float* B1 = EXPERT ? (g_wg + (size_t)e * DM * FE) : g_wsg2;
    const float* B2 = EXPERT ? (g_wu + (size_t)e * DM * FE) : g_wsu;
    float* C = EXPERT ? (g_acte + (size_t)e * NTOK * FE) : g_acts;
    const int* rl = g_list + e * NTOK;

    const int tid = threadIdx.x, l = tid & 31, w = tid >> 5;
    const uint32_t smb = smem_u32(sm);

    // A: 128 rows x 16 chunks; thread -> rows (tid>>4)+16p, chunk tid&15
    const int arow = tid >> 4, akq = tid & 15;
    int adst[8];
    uint32_t asz[8];
    const float* Asrc[8];
#pragma unroll
    for (int p = 0; p < 8; p++) {
        int rloc = arow + 16 * p;
        adst[p] = rloc * ASTR + akq * 4;
        int r = row0 + rloc;
        asz[p] = r < M ? 16u : 0u;
        int s = r < M ? (EXPERT ? rl[r] : r) : 0;
        Asrc[p] = g_ht + (size_t)s * DM + akq * 4;
    }
    // B: 64 rows x 32 chunks per matrix; thread -> k rows (tid>>5)+8j, chunk tid&31
    const int bk_ = tid >> 5, bnq = tid & 31;
    int bdst[8];
    const float* Bsrc1[8];
    const float* Bsrc2[8];
#pragma unroll
    for (int j = 0; j < 8; j++) {
        int kk = bk_ + 8 * j;
        bdst[j] = kk * B1STR + bnq * 4;
        Bsrc1[j] = B1 + (size_t)kk * ldb + n0 + bnq * 4;
        Bsrc2[j] = B2 + (size_t)kk * ldb + n0 + bnq * 4;
    }

    const int wm_i = w >> 2, wn_i = w & 3, grp = l >> 2, tg = l & 3;

    float c1[4][4][4], c2[4][4][4];
#pragma unroll
    for (int i = 0; i < 4; i++)
#pragma unroll
        for (int j = 0; j < 4; j++)
#pragma unroll
            for (int q = 0; q < 4; q++) { c1[i][j][q] = 0.f; c2[i][j][q] = 0.f; }

    const int T = DM / 64;
    G1_CP(0, 0) CPCOMMIT();
    int buf = 0;
    for (int t = 0; t < T; t++) {
        CPWAIT(0);
        __syncthreads();
        if (t + 1 < T) { G1_CP(t + 1, buf ^ 1) CPCOMMIT(); }
        G1_COMP(buf)
        buf ^= 1;
    }

    // epilogue: silu(gate)*up, rounded to tf32 (so gemm2 can stage raw)
    const int ldc = ldb;
#pragma unroll
    for (int im = 0; im < 4; im++) {
        int r = row0 + wm_i * 64 + im * 16 + grp;
#pragma unroll
        for (int in = 0; in < 4; in++) {
            int cc = n0 + wn_i * 32 + in * 8 + 2 * tg;
            if (r < M) {
                float g0 = c1[im][in][0], u0 = c2[im][in][0];
                float g1 = c1[im][in][1], u1 = c2[im][in][1];
                float2 o;
                o.x = tf32r(g0 * (1.f / (1.f + __expf(-g0))) * u0);
                o.y = tf32r(g1 * (1.f / (1.f + __expf(-g1))) * u1);
                *reinterpret_cast<float2*>(&C[(size_t)r * ldc + cc]) = o;
            }
            if (r + 8 < M) {
                float g0 = c1[im][in][2], u0 = c2[im][in][2];
                float g1 = c1[im][in][3], u1 = c2[im][in][3];
                float2 o;
                o.x = tf32r(g0 * (1.f / (1.f + __expf(-g0))) * u0);
                o.y = tf32r(g1 * (1.f / (1.f + __expf(-g1))) * u1);
                *reinterpret_cast<float2*>(&C[(size_t)(r + 8) * ldc + cc]) = o;
            }
        }
    }
}

// ---------------- GEMM2: M=128 N=256 BK=64; shared->out, expert->g_eout -------
#define G2_CP(T_, BUF)                                                           \
    {                                                                            \
        const int _k0 = (T_) * 64;                                               \
        const size_t _bo = (size_t)_k0 * DM;                                     \
        uint32_t _d = smb + (BUF) * (G2_STAGE * 4);                              \
        _Pragma("unroll") for (int p = 0; p < 8; p++)                            \
            CP16Z(_d + adst[p] * 4, Asrc[p] + _k0, asz[p]);                      \
        _Pragma("unroll") for (int j = 0; j < 16; j++)                           \
            CP16(_d + (ASZ + bdst[j]) * 4, Bsrc[j] + _bo);                       \
    }

#define G2_COMP(BUF)                                                             \
    {                                                                            \
        const float* SA = sm + (BUF) * G2_STAGE;                                 \
        const float* SB = SA + ASZ;                                              \
        _Pragma("unroll") for (int kt = 0; kt < 8; kt++) {                       \
            const int ks = kt * 8;                                               \
            uint32_t a[4][4], b[8][2];                                           \
            _Pragma("unroll") for (int im = 0; im < 4; im++) {                   \
                const int m0 = wm_i * 64 + im * 16;                              \
                a[im][0] = au(SA[(m0 + grp) * ASTR + ks + tg]);                  \
                a[im][1] = au(SA[(m0 + 8 + grp) * ASTR + ks + tg]);              \
                a[im][2] = au(SA[(m0 + grp) * ASTR + ks + tg + 4]);              \
                a[im][3] = au(SA[(m0 + 8 + grp) * ASTR + ks + tg + 4]);          \
            }                                                                    \
            _Pragma("unroll") for (int in = 0; in < 8; in++) {                   \
                const int nb = wn_i * 64 + in * 8 + grp;                         \
                b[in][0] = au(SB[(ks + tg) * B2STR + nb]);                       \
                b[in][1] = au(SB[(ks + tg + 4) * B2STR + nb]);                   \
            }                                                                    \
            _Pragma("unroll") for (int im = 0; im < 4; im++)                     \
                _Pragma("unroll") for (int in = 0; in < 8; in++)                 \
                    mma8(c[im][in], a[im], b[in]);                               \
        }                                                                        \
    }

template <bool EXPERT>
__global__ __launch_bounds__(256, 1)
void gemm2_kernel(float* __restrict__ out) {
    extern __shared__ float sm[];
    const int e = EXPERT ? blockIdx.z : 0;
    const int M = EXPERT ? g_cnt[e] : NTOK;
    const int row0 = blockIdx.y * 128;
    if (row0 >= M) return;
    const int n0 = blockIdx.x * 256;
    const int K = EXPERT ? FE : FS;
    const float* Aact = EXPERT ? (g_acte + (size_t)e * NTOK * FE) : g_acts;
    const float* B = EXPERT ? (g_wd + (size_t)e * FE * DM) : g_wsd;

    const int tid = threadIdx.x, l = tid & 31, w = tid >> 5;
    const uint32_t smb = smem_u32(sm);

    const int arow = tid >> 4, akq = tid & 15;
    int adst[8];
    uint32_t asz[8];
    const float* Asrc[8];
#pragma unroll
    for (int p = 0; p < 8; p++) {
        int rloc = arow + 16 * p;
        adst[p] = rloc * ASTR + akq * 4;
        int r = row0 + rloc;
        asz[p] = r < M ? 16u : 0u;
        Asrc[p] = Aact + (size_t)(r < M ? r : 0) * K + akq * 4;
    }
    // B: 64 rows x 64 chunks; thread -> k rows (tid>>6)+4j, chunk tid&63
    const int bk_ = tid >> 6, bnq = tid & 63;
    int bdst[16];
    const float* Bsrc[16];
#pragma unroll
    for (int j = 0; j < 16; j++) {
        int kk = bk_ + 4 * j;
        bdst[j] = kk * B2STR + bnq * 4;
        Bsrc[j] = B + (size_t)kk * DM + n0 + bnq * 4;
    }

    const int wm_i = w >> 2, wn_i = w & 3, grp = l >> 2, tg = l & 3;

    float c[4][8][4];
#pragma unroll
    for (int i = 0; i < 4; i++)
#pragma unroll
        for (int j = 0; j < 8; j++)
#pragma unroll
            for (int q = 0; q < 4; q++) c[i][j][q] = 0.f;

    const int T = K / 64;
    G2_CP(0, 0) CPCOMMIT();
    int buf = 0;
    for (int t = 0; t < T; t++) {
        CPWAIT(0);
        __syncthreads();
        if (t + 1 < T) { G2_CP(t + 1, buf ^ 1) CPCOMMIT(); }
        G2_COMP(buf)
        buf ^= 1;
    }

    // epilogue: shared -> out (scaled); expert -> compact g_eout rows (plain)
#pragma unroll
    for (int im = 0; im < 4; im++) {
        int r = row0 + wm_i * 64 + im * 16 + grp;
        float s0 = 0.f, s1 = 0.f;
        if (!EXPERT) {
            if (r < M)     s0 = g_sg[r];
            if (r + 8 < M) s1 = g_sg[r + 8];
        }
#pragma unroll
        for (int in = 0; in < 8; in++) {
            int cc = n0 + wn_i * 64 + in * 8 + 2 * tg;
            if (r < M) {
                if (EXPERT) {
                    float2 o; o.x = c[im][in][0]; o.y = c[im][in][1];
                    *reinterpret_cast<float2*>(
                        &g_eout[((size_t)e * NTOK + r) * DM + cc]) = o;
                } else {
                    float2 o; o.x = s0 * c[im][in][0]; o.y = s0 * c[im][in][1];
                    *reinterpret_cast<float2*>(&out[(size_t)r * DM + cc]) = o;
                }
            }
            if (r + 8 < M) {
                if (EXPERT) {
                    float2 o; o.x = c[im][in][2]; o.y = c[im][in][3];
                    *reinterpret_cast<float2*>(
                        &g_eout[((size_t)e * NTOK + r + 8) * DM + cc]) = o;
                } else {
                    float2 o; o.x = s1 * c[im][in][2]; o.y = s1 * c[im][in][3];
                    *reinterpret_cast<float2*>(&out[(size_t)(r + 8) * DM + cc]) = o;
                }
            }
        }
    }
}

// ---------------- combine: out[t] += w0*eout[idx0] + w1*eout[idx1] ------------
__global__ void combine_kernel(float* __restrict__ out) {
    int t = blockIdx.x;
    int d = threadIdx.x;
    int i0 = g_rowidx[2 * t], i1 = g_rowidx[2 * t + 1];
    float w0 = g_wt[2 * t], w1 = g_wt[2 * t + 1];
    const float4* r0 = reinterpret_cast<const float4*>(g_eout + (size_t)i0 * DM);
    const float4* r1 = reinterpret_cast<const float4*>(g_eout + (size_t)i1 * DM);
    float4* o = reinterpret_cast<float4*>(out + (size_t)t * DM);
#pragma unroll
    for (int j = 0; j < 2; j++) {
        int idx = d + 256 * j;
        float4 a = r0[idx], b = r1[idx], c = o[idx];
        c.x += w0 * a.x + w1 * b.x;
        c.y += w0 * a.y + w1 * b.y;
        c.z += w0 * a.z + w1 * b.z;
        c.w += w0 * a.w + w1 * b.w;
        o[idx] = c;
    }
}

// ---------------- launch ----------------
extern "C" void kernel_launch(void* const* d_in, const int* in_sizes, int n_in,
                              void* d_out, int out_size) {
    const float* h       = (const float*)d_in[0];
    const float* gate_w  = (const float*)d_in[1];
    const float* w_gate  = (const float*)d_in[2];
    const float* w_up    = (const float*)d_in[3];
    const float* w_down  = (const float*)d_in[4];
    const float* ws_gate = (const float*)d_in[5];
    const float* ws_up   = (const float*)d_in[6];
    const float* ws_down = (const float*)d_in[7];
    const float* wsg     = (const float*)d_in[8];
    float* out = (float*)d_out;

    cudaFuncSetAttribute(gemm1_kernel<false>, cudaFuncAttributeMaxDynamicSharedMemorySize, G1_SMEM);
    cudaFuncSetAttribute(gemm1_kernel<true>,  cudaFuncAttributeMaxDynamicSharedMemorySize, G1_SMEM);
    cudaFuncSetAttribute(gemm2_kernel<false>, cudaFuncAttributeMaxDynamicSharedMemorySize, G2_SMEM);
    cudaFuncSetAttribute(gemm2_kernel<true>,  cudaFuncAttributeMaxDynamicSharedMemorySize, G2_SMEM);

    round_kernel<<<dim3(512, 7), 256>>>(h, w_gate, w_up, w_down, ws_gate, ws_up, ws_down);
    router_kernel<<<NTOK / 8, 256>>>(h, gate_w, wsg);
    build_lists_kernel<<<NE, 256>>>();

    gemm1_kernel<false><<<dim3(FS / 128, NTOK / 128), 256, G1_SMEM>>>();
    gemm1_kernel<true><<<dim3(FE / 128, NTOK / 128, NE), 256, G1_SMEM>>>();
    gemm2_kernel<false><<<dim3(DM / 256, NTOK / 128), 256, G2_SMEM>>>(out);
    gemm2_kernel<true><<<dim3(DM / 256, NTOK / 128, NE), 256, G2_SMEM>>>(out);
    combine_kernel<<<NTOK, 256>>>(out);
}